// round 7
// baseline (speedup 1.0000x reference)
#include <cuda_runtime.h>
#include <cuda_bf16.h>

// out shape (1, 8, 4096, 4096) fp32, 512 MiB of stores.
// c in 0..3:  out[c][i][j] = table[seq[i]*4 + c]      (row splat, constant over j)
// c in 4..7:  out[c][i][j] = table[seq[j]*4 + (c-4)]  (identical 16KB pattern every i)
//
// Tile 4 rows per block: pattern channels compute lookups ONCE, store 4x.
// Each block writes one contiguous 64KB extent with streaming float4 stores.

#define L 4096
#define NB 4
#define TILE_I 4

__global__ __launch_bounds__(256, 8)
void seq_embed_kernel(const int* __restrict__ seq,
                      const float* __restrict__ table,
                      float* __restrict__ out)
{
    const int i0 = blockIdx.x * TILE_I;   // 0,4,...,4092
    const int c  = blockIdx.y;            // 0..7
    const int t  = threadIdx.x;

    // float4 view: row stride = L/4 = 1024 float4 slots
    float4* base = reinterpret_cast<float4*>(
        out + (((size_t)c * L) + (size_t)i0) * (size_t)L);

    if (c < NB) {
        // 4 splat rows: one value per row, broadcast load
#pragma unroll
        for (int r = 0; r < TILE_I; ++r) {
            const float v = __ldg(&table[__ldg(&seq[i0 + r]) * NB + c]);
            const float4 f4 = make_float4(v, v, v, v);
            float4* row = base + (size_t)r * (L / 4);
#pragma unroll
            for (int k = 0; k < 4; ++k)
                __stcs(row + t + 256 * k, f4);
        }
    } else {
        const int cc = c - NB;
        __shared__ float tbl[NB * NB];
        if (t < NB * NB) tbl[t] = table[t];
        __syncthreads();

        // Compute this thread's 16 pattern floats ONCE (reused for 4 rows)
        const int4* seq4 = reinterpret_cast<const int4*>(seq);
        float4 vals[4];
#pragma unroll
        for (int k = 0; k < 4; ++k) {
            const int4 s = __ldg(seq4 + t + 256 * k);  // 16KB total, L2-resident
            vals[k] = make_float4(tbl[s.x * NB + cc],
                                  tbl[s.y * NB + cc],
                                  tbl[s.z * NB + cc],
                                  tbl[s.w * NB + cc]);
        }

        // Store the same pattern to 4 consecutive rows (64KB contiguous/block)
#pragma unroll
        for (int r = 0; r < TILE_I; ++r) {
            float4* row = base + (size_t)r * (L / 4);
#pragma unroll
            for (int k = 0; k < 4; ++k)
                __stcs(row + t + 256 * k, vals[k]);
        }
    }
}

extern "C" void kernel_launch(void* const* d_in, const int* in_sizes, int n_in,
                              void* d_out, int out_size)
{
    const int*   seq   = (const int*)d_in[0];    // seq_ids (int32)
    const float* table = (const float*)d_in[1];  // base_table (4x4)
    float*       out   = (float*)d_out;          // (1, 8, 4096, 4096) fp32

    dim3 grid(L / TILE_I, 2 * NB);
    seq_embed_kernel<<<grid, 256>>>(seq, table, out);
}